// round 2
// baseline (speedup 1.0000x reference)
#include <cuda_runtime.h>

namespace {

constexpr int BATCH   = 4;
constexpr int NIN     = 1024;
constexpr int NOUT    = 1024;
constexpr int CH      = 8;    // density + 7 raw channels
constexpr int OC      = 16;
constexpr int OPB     = 8;    // outputs per block -> grid = 512
constexpr int THREADS = 256;
constexpr int WARPS   = THREADS / 32;   // 8
// each warp covers 128 i; each lane: 32 iterations (i_sub interleave of 4)

__device__ __forceinline__ float ex2_approx(float x) {
    float y;
    asm("ex2.approx.f32 %0, %1;" : "=f"(y) : "f"(x));
    return y;
}

__global__ __launch_bounds__(THREADS, 4)
void convdeepset_kernel(const float* __restrict__ cx,     // [B, NIN, 1]
                        const float* __restrict__ cy,     // [B, NIN, 7]
                        const float* __restrict__ t,      // [B, NOUT, 1]
                        const float* __restrict__ sigma,  // [8]
                        const float* __restrict__ W,      // [8, 16]
                        const float* __restrict__ bias,   // [16]
                        float* __restrict__ out)          // [B, NOUT, 16]
{
    // Packed row: {x, y1, y2, y3}, {y4, y5, y6, y7}  -> 2 x LDS.128 per pair
    __shared__ float4 sxy[NIN][2];                 // 32 KB
    __shared__ float  spart[WARPS][OPB][CH];       // 2 KB
    __shared__ float  sagg2[OPB][CH];              // 256 B

    const int b     = blockIdx.x >> 7;             // / (NOUT/OPB)
    const int otile = blockIdx.x & 127;
    const int tid   = threadIdx.x;
    const int warp  = tid >> 5;
    const int lane  = tid & 31;
    const int o_l   = lane & 7;                    // output within tile
    const int i_sub = lane >> 3;                   // 0..3 interleaved i slice

    // Per-channel exponent computed redundantly per thread (no extra sync):
    // w = exp(-0.5*d2/s^2) = exp2(beta*d2), beta = -0.5*log2(e)/exp(2*sigma)
    float betas[CH];
    bool uni = true;
    #pragma unroll
    for (int c = 0; c < CH; c++) {
        float s = expf(sigma[c]);
        betas[c] = -0.5f * 1.4426950408889634f / (s * s);
    }
    #pragma unroll
    for (int c = 1; c < CH; c++) uni &= (betas[c] == betas[0]);

    // Stage packed {x, y...} rows into shared
    {
        float* s = reinterpret_cast<float*>(sxy);
        for (int idx = tid; idx < NIN * CH; idx += THREADS) {
            int i = idx >> 3, c = idx & 7;
            s[idx] = (c == 0) ? cx[b * NIN + i]
                              : cy[(b * NIN + i) * 7 + (c - 1)];
        }
    }
    __syncthreads();

    const float t_o = t[b * NOUT + otile * OPB + o_l];

    float acc[CH];
    #pragma unroll
    for (int c = 0; c < CH; c++) acc[c] = 0.0f;

    // Warp covers i in [warp*128, warp*128+128); lane strides by 4 from i_sub.
    const float4* row = &sxy[warp * 128 + i_sub][0];

    if (uni) {
        const float beta0 = betas[0];
        #pragma unroll 8
        for (int j = 0; j < 32; j++) {
            float4 p0 = row[0];
            float4 p1 = row[1];
            float d = p0.x - t_o;
            float w = ex2_approx(beta0 * (d * d));
            acc[0] += w;          // density channel: y == 1
            acc[1] += p0.y * w;  acc[2] += p0.z * w;  acc[3] += p0.w * w;
            acc[4] += p1.x * w;  acc[5] += p1.y * w;
            acc[6] += p1.z * w;  acc[7] += p1.w * w;
            row += 8;            // advance 4 packed rows
        }
    } else {
        #pragma unroll 4
        for (int j = 0; j < 32; j++) {
            float4 p0 = row[0];
            float4 p1 = row[1];
            float d = p0.x - t_o;
            float u = d * d;
            acc[0] += ex2_approx(betas[0] * u);
            acc[1] += p0.y * ex2_approx(betas[1] * u);
            acc[2] += p0.z * ex2_approx(betas[2] * u);
            acc[3] += p0.w * ex2_approx(betas[3] * u);
            acc[4] += p1.x * ex2_approx(betas[4] * u);
            acc[5] += p1.y * ex2_approx(betas[5] * u);
            acc[6] += p1.z * ex2_approx(betas[6] * u);
            acc[7] += p1.w * ex2_approx(betas[7] * u);
            row += 8;
        }
    }

    // Reduce the 4 i_sub slices within the warp (lanes with same o_l converge)
    #pragma unroll
    for (int c = 0; c < CH; c++) {
        acc[c] += __shfl_xor_sync(0xffffffffu, acc[c], 8);
        acc[c] += __shfl_xor_sync(0xffffffffu, acc[c], 16);
    }
    if (lane < 8) {
        *reinterpret_cast<float4*>(&spart[warp][o_l][0]) =
            make_float4(acc[0], acc[1], acc[2], acc[3]);
        *reinterpret_cast<float4*>(&spart[warp][o_l][4]) =
            make_float4(acc[4], acc[5], acc[6], acc[7]);
    }
    __syncthreads();

    // Cross-warp reduce + normalize (64 threads = warps 0,1 fully active)
    if (tid < OPB * CH) {
        int ol = tid >> 3, c = tid & 7;
        float s = 0.0f;
        #pragma unroll
        for (int w2 = 0; w2 < WARPS; w2++) s += spart[w2][ol][c];
        // den for this ol lives in the c==0 lane of the same warp
        float den = __shfl_sync(0xffffffffu, s, lane & ~7u);
        sagg2[ol][c] = (c == 0) ? s : s / (den + 1e-8f);
    }
    __syncthreads();

    // Epilogue: out[o][k] = b[k] + sum_c agg2[o][c] * W[c][k]
    if (tid < OPB * OC) {
        int ol = tid >> 4, k = tid & 15;
        float v = __ldg(&bias[k]);
        #pragma unroll
        for (int c = 0; c < CH; c++) v += sagg2[ol][c] * __ldg(&W[c * OC + k]);
        out[(b * NOUT + otile * OPB + ol) * OC + k] = v;
    }
}

} // namespace

extern "C" void kernel_launch(void* const* d_in, const int* in_sizes, int n_in,
                              void* d_out, int out_size) {
    const float* cx = (const float*)d_in[0];  // context_x
    const float* cy = (const float*)d_in[1];  // context_y
    const float* t  = (const float*)d_in[2];  // t
    const float* sg = (const float*)d_in[3];  // sigma
    const float* W  = (const float*)d_in[4];  // W
    const float* bi = (const float*)d_in[5];  // b
    float* out = (float*)d_out;

    dim3 grid(BATCH * (NOUT / OPB));          // 512 blocks
    convdeepset_kernel<<<grid, THREADS>>>(cx, cy, t, sg, W, bi, out);
}

// round 3
// speedup vs baseline: 1.0051x; 1.0051x over previous
#include <cuda_runtime.h>

namespace {

constexpr int BATCH   = 4;
constexpr int NIN     = 1024;
constexpr int NOUT    = 1024;
constexpr int CH      = 8;    // density + 7 raw channels
constexpr int OC      = 16;
constexpr int OPB     = 32;   // outputs per block (= warp width)
constexpr int THREADS = 512;
constexpr int WARPS   = THREADS / 32;   // 16
constexpr int IPW     = NIN / WARPS;    // 64 context points per warp

__device__ __forceinline__ float ex2_approx(float x) {
    float y;
    asm("ex2.approx.f32 %0, %1;" : "=f"(y) : "f"(x));
    return y;
}

__global__ __launch_bounds__(THREADS, 1)
void convdeepset_kernel(const float* __restrict__ cx,     // [B, NIN, 1]
                        const float* __restrict__ cy,     // [B, NIN, 7]
                        const float* __restrict__ t,      // [B, NOUT, 1]
                        const float* __restrict__ sigma,  // [8]
                        const float* __restrict__ W,      // [8, 16]
                        const float* __restrict__ bias,   // [16]
                        float* __restrict__ out)          // [B, NOUT, 16]
{
    // Packed row per i: {x, y1, y2, y3}, {y4, y5, y6, y7} -> 2 broadcast LDS.128
    __shared__ float4 sxy[NIN][2];          // 32 KB; reused for partials later
    __shared__ float  sagg2[OPB][CH];       // 1 KB

    const int b     = blockIdx.x >> 5;      // / 32
    const int otile = blockIdx.x & 31;
    const int tid   = threadIdx.x;
    const int warp  = tid >> 5;
    const int lane  = tid & 31;

    // Per-channel exponent, computed redundantly per thread:
    // w = exp(-0.5*d2/s^2) = exp2(beta*d2), beta = -0.5*log2(e)/exp(2*sigma)
    float betas[CH];
    bool uni = true;
    #pragma unroll
    for (int c = 0; c < CH; c++) {
        float s = expf(sigma[c]);
        betas[c] = -0.5f * 1.4426950408889634f / (s * s);
    }
    #pragma unroll
    for (int c = 1; c < CH; c++) uni &= (betas[c] == betas[0]);

    // Stage packed {x, y...} rows into shared (16 loads per thread)
    {
        float* s = reinterpret_cast<float*>(sxy);
        for (int idx = tid; idx < NIN * CH; idx += THREADS) {
            int i = idx >> 3, c = idx & 7;
            s[idx] = (c == 0) ? cx[b * NIN + i]
                              : cy[(b * NIN + i) * 7 + (c - 1)];
        }
    }

    // Each lane owns one output o; the whole warp walks the same i-slice.
    const float t_o = t[b * NOUT + otile * OPB + lane];

    __syncthreads();

    float acc[CH];
    #pragma unroll
    for (int c = 0; c < CH; c++) acc[c] = 0.0f;

    const float4* row = &sxy[warp * IPW][0];

    if (uni) {
        const float beta0 = betas[0];
        #pragma unroll 8
        for (int j = 0; j < IPW; j++) {
            float4 p0 = row[0];              // broadcast: all lanes same addr
            float4 p1 = row[1];
            float d = p0.x - t_o;
            float w = ex2_approx(beta0 * (d * d));
            acc[0] += w;                     // density channel: y == 1
            acc[1] += p0.y * w;  acc[2] += p0.z * w;  acc[3] += p0.w * w;
            acc[4] += p1.x * w;  acc[5] += p1.y * w;
            acc[6] += p1.z * w;  acc[7] += p1.w * w;
            row += 2;
        }
    } else {
        #pragma unroll 4
        for (int j = 0; j < IPW; j++) {
            float4 p0 = row[0];
            float4 p1 = row[1];
            float d = p0.x - t_o;
            float u = d * d;
            acc[0] += ex2_approx(betas[0] * u);
            acc[1] += p0.y * ex2_approx(betas[1] * u);
            acc[2] += p0.z * ex2_approx(betas[2] * u);
            acc[3] += p0.w * ex2_approx(betas[3] * u);
            acc[4] += p1.x * ex2_approx(betas[4] * u);
            acc[5] += p1.y * ex2_approx(betas[5] * u);
            acc[6] += p1.z * ex2_approx(betas[6] * u);
            acc[7] += p1.w * ex2_approx(betas[7] * u);
            row += 2;
        }
    }

    // All warps done reading sxy -> safe to alias it for partials.
    __syncthreads();
    {
        float* spart = reinterpret_cast<float*>(sxy);  // [WARPS][OPB][CH]
        float4* dst = reinterpret_cast<float4*>(&spart[(warp * OPB + lane) * CH]);
        dst[0] = make_float4(acc[0], acc[1], acc[2], acc[3]);
        dst[1] = make_float4(acc[4], acc[5], acc[6], acc[7]);
    }
    __syncthreads();

    // Cross-warp reduce + normalize: 256 threads, one per (o, c)
    if (tid < OPB * CH) {
        const float* spart = reinterpret_cast<const float*>(sxy);
        int o = tid >> 3, c = tid & 7;
        float s = 0.0f;
        #pragma unroll
        for (int w2 = 0; w2 < WARPS; w2++)
            s += spart[(w2 * OPB + o) * CH + c];
        // den for this o lives in the c==0 lane of the same group of 8
        float den = __shfl_sync(0xffffffffu, s, lane & ~7u);
        sagg2[o][c] = (c == 0) ? s : s / (den + 1e-8f);
    }
    __syncthreads();

    // Epilogue: out[o][k] = bias[k] + sum_c agg2[o][c] * W[c][k]
    {
        int o = tid >> 4, k = tid & 15;    // 32 x 16 = 512 threads exactly
        float v = __ldg(&bias[k]);
        #pragma unroll
        for (int c = 0; c < CH; c++) v += sagg2[o][c] * __ldg(&W[c * OC + k]);
        out[(b * NOUT + otile * OPB + o) * OC + k] = v;
    }
}

} // namespace

extern "C" void kernel_launch(void* const* d_in, const int* in_sizes, int n_in,
                              void* d_out, int out_size) {
    const float* cx = (const float*)d_in[0];  // context_x
    const float* cy = (const float*)d_in[1];  // context_y
    const float* t  = (const float*)d_in[2];  // t
    const float* sg = (const float*)d_in[3];  // sigma
    const float* W  = (const float*)d_in[4];  // W
    const float* bi = (const float*)d_in[5];  // b
    float* out = (float*)d_out;

    dim3 grid(BATCH * (NOUT / OPB));          // 128 blocks of 512 threads
    convdeepset_kernel<<<grid, THREADS>>>(cx, cy, t, sg, W, bi, out);
}